// round 10
// baseline (speedup 1.0000x reference)
#include <cuda_runtime.h>
#include <math.h>

#define Bc   8
#define Cc   48
#define Nn   4096
#define KK   9
#define NBc  32768          // B*N
#define Ec   (Bc*Nn*KK)     // 294912

// -------- scratch (static device globals; no allocation) --------
__device__ float g_xnT[Bc*Cc*Nn];   // normalized features, CHANNEL-major [b][c][n]
__device__ float g_nodes[NBc*Cc];   // raw features, node-major
__device__ float g_sq[NBc];         // sum of squares of normalized row
__device__ int   g_nn[NBc*KK];      // knn indices (within batch, 0..N-1)
__device__ int   g_deg[NBc];
__device__ float g_dinv[NBc];
__device__ float g_tx1[NBc*Cc];

// faithful replication of jnp.linspace(0, 8, E).astype(int32):
// value_i = fl(fl(i) * fl(8/294911)), truncated toward zero.
__device__ __forceinline__ int edge_count(int i) {
    const float STEP = 8.0f / 294911.0f;
    return (int)((float)i * STEP);
}

// monotone float->uint map: preserves < ordering for all finite floats
__device__ __forceinline__ unsigned int fmono(float d) {
    unsigned int u = __float_as_uint(d);
    return (u & 0x80000000u) ? ~u : (u | 0x80000000u);
}

// packed f32x2 helpers (element-wise IEEE fp32: bit-identical to 2x fmaf)
__device__ __forceinline__ unsigned long long pack_dup(float v) {
    unsigned long long r;
    asm("mov.b64 %0, {%1, %1};" : "=l"(r) : "r"(__float_as_uint(v)));
    return r;
}
__device__ __forceinline__ void fma2(unsigned long long& acc,
                                     unsigned long long a, unsigned long long b) {
    asm("fma.rn.f32x2 %0, %1, %2, %0;" : "+l"(acc) : "l"(a), "l"(b));
}
__device__ __forceinline__ void unpack2(unsigned long long p, float& lo, float& hi) {
    unsigned int l, h;
    asm("mov.b64 {%0, %1}, %2;" : "=r"(l), "=r"(h) : "l"(p));
    lo = __uint_as_float(l); hi = __uint_as_float(h);
}

// ---------------- prep: normalize; emit channel-major + node-major ----------------
__global__ void prep_kernel(const float* __restrict__ x) {
    int node = blockIdx.x * blockDim.x + threadIdx.x;
    if (node >= NBc) return;
    int b = node >> 12, n = node & (Nn - 1);
    const float* xb = x + (size_t)b * Cc * Nn + n;
    float v[Cc];
    float ss = 0.f;
#pragma unroll
    for (int c = 0; c < Cc; c++) { v[c] = xb[c * Nn]; ss += v[c] * v[c]; }
    float m = fmaxf(sqrtf(ss), 1e-12f);
    float sq = 0.f;
    float* xT = g_xnT + (size_t)b * Cc * Nn + n;
#pragma unroll
    for (int c = 0; c < Cc; c++) {
        float xv = v[c] / m;
        xT[c * Nn]             = xv;   // channel-major (coalesced across threads)
        g_nodes[node * Cc + c] = v[c];
        sq += xv * xv;
    }
    g_sq[node]  = sq;
    g_deg[node] = 0;
}

// ---------------- KNN: tiled distances + fused top-9 (u64 reg lists) ----------------
// Block 256: each thread owns 4 query rows x 8 cand cols (QT=128, MT=64).
// ms tiles use a two-granule permutation: col c -> offset g*32 + cs*4 + e
// (cs=c>>3, g=(c&7)>>2, e=c&3), so each m LDS.128's 8 distinct addresses
// span all 32 banks -> 1 crossbar phase, 128 distinct bytes.
#define QT 128
#define MT 64

__global__ __launch_bounds__(256, 2) void knn_kernel() {
    __shared__ float qs[Cc * QT];        // [k*128 + r]                (24 KB)
    __shared__ float ms[2][Cc * MT];     // [k*64 + perm(c)] ping-pong (24 KB)
    __shared__ float sqm[2][MT];

    int t    = threadIdx.x;
    int r0   = (t >> 3) * 4;      // 0,4,...,124
    int cs   = t & 7;             // column segment 0..7 (8 cols each)
    int cseg = cs * 8;
    int b    = blockIdx.y;
    int qBase = blockIdx.x * QT;
    int nodeBase = b * Nn;
    const float* xT = g_xnT + (size_t)b * Cc * Nn;

    // qs: straight coalesced copy (already k-major). Cc*QT/4 = 1536 float4s.
    for (int i = t; i < Cc * 32; i += 256) {
        int k = i >> 5, c4 = i & 31;
        *(float4*)&qs[k * QT + c4 * 4] =
            *(const float4*)&xT[k * Nn + qBase + c4 * 4];
    }
    // preload tile 0 with two-granule permutation:
    // source float4 #c4 (cols c4*4..c4*4+3) -> dest float offset (c4&1)*32 + (c4>>1)*4
    for (int i = t; i < Cc * 16; i += 256) {
        int k = i >> 4, c4 = i & 15;
        int dp = ((c4 & 1) << 5) + ((c4 >> 1) << 2);
        *(float4*)&ms[0][k * MT + dp] =
            *(const float4*)&xT[k * Nn + c4 * 4];
    }
    if (t < MT) sqm[0][t] = g_sq[nodeBase + t];
    float sqq[4];
#pragma unroll
    for (int r = 0; r < 4; r++) sqq[r] = g_sq[nodeBase + qBase + r0 + r];

    // sentinel: (d=+INF, idx=0xFFFFFFFF)
    unsigned long long lst[4][KK];
#pragma unroll
    for (int r = 0; r < 4; r++)
#pragma unroll
        for (int s = 0; s < KK; s++) lst[r][s] = 0xFF800000FFFFFFFFULL;
    unsigned int thr[4];   // fmono-form thresholds (u32 compare == float compare)
#pragma unroll
    for (int r = 0; r < 4; r++) thr[r] = 0xFF800000u;

    __syncthreads();

    int p = 0;
    for (int mb = 0; mb < Nn; mb += MT) {
        // prefetch next tile into the other buffer
        if (mb + MT < Nn) {
            for (int i = t; i < Cc * 16; i += 256) {
                int k = i >> 4, c4 = i & 15;
                int dp = ((c4 & 1) << 5) + ((c4 >> 1) << 2);
                *(float4*)&ms[1 - p][k * MT + dp] =
                    *(const float4*)&xT[k * Nn + (mb + MT) + c4 * 4];
            }
            if (t < MT) sqm[1 - p][t] = g_sq[nodeBase + mb + MT + t];
        }

        const float* msp = ms[p];
        unsigned long long a[4][4];   // [row][col-pair]: 4 f32x2 per row = 8 cols
#pragma unroll
        for (int r = 0; r < 4; r++)
#pragma unroll
            for (int j = 0; j < 4; j++) a[r][j] = 0ULL;

#pragma unroll 6
        for (int k = 0; k < Cc; k++) {
            float4 q4 = *(const float4*)&qs[k * QT + r0];
            unsigned long long q0 = pack_dup(q4.x);
            unsigned long long q1 = pack_dup(q4.y);
            unsigned long long q2 = pack_dup(q4.z);
            unsigned long long q3 = pack_dup(q4.w);
            const unsigned long long* mk =
                (const unsigned long long*)&msp[k * MT];
            unsigned long long m0 = mk[cs * 2],      m1 = mk[cs * 2 + 1];
            unsigned long long m2 = mk[16 + cs * 2], m3 = mk[16 + cs * 2 + 1];
            fma2(a[0][0], q0, m0); fma2(a[0][1], q0, m1);
            fma2(a[0][2], q0, m2); fma2(a[0][3], q0, m3);
            fma2(a[1][0], q1, m0); fma2(a[1][1], q1, m1);
            fma2(a[1][2], q1, m2); fma2(a[1][3], q1, m3);
            fma2(a[2][0], q2, m0); fma2(a[2][1], q2, m1);
            fma2(a[2][2], q2, m2); fma2(a[2][3], q2, m3);
            fma2(a[3][0], q3, m0); fma2(a[3][1], q3, m1);
            fma2(a[3][2], q3, m2); fma2(a[3][3], q3, m3);
        }

#pragma unroll
        for (int r = 0; r < 4; r++) {
            float acc[8];
#pragma unroll
            for (int j = 0; j < 4; j++) unpack2(a[r][j], acc[2 * j], acc[2 * j + 1]);
#pragma unroll
            for (int j = 0; j < 8; j++) {
                float d = (sqq[r] + sqm[p][cseg + j]) - 2.f * acc[j];
                unsigned int dm = fmono(d);
                if (dm <= thr[r]) {
                    int mi = mb + cseg + j;
                    unsigned long long key =
                        ((unsigned long long)dm << 32) | (unsigned int)mi;
                    if (key < lst[r][KK - 1]) {
                        lst[r][KK - 1] = key;
#pragma unroll
                        for (int s = KK - 1; s > 0; --s) {
                            if (lst[r][s] < lst[r][s - 1]) {
                                unsigned long long tmp = lst[r][s];
                                lst[r][s] = lst[r][s - 1]; lst[r][s - 1] = tmp;
                            }
                        }
                        thr[r] = (unsigned int)(lst[r][KK - 1] >> 32);
                    }
                }
            }
        }

        __syncthreads();
        p ^= 1;
    }

    // butterfly merge across the 8 threads sharing this row quartet
#pragma unroll
    for (int delta = 1; delta <= 4; delta <<= 1) {
#pragma unroll
        for (int r = 0; r < 4; r++) {
            unsigned long long oth[KK];
#pragma unroll
            for (int s = 0; s < KK; s++)
                oth[s] = __shfl_xor_sync(0xffffffffu, lst[r][s], delta);
#pragma unroll
            for (int s = 0; s < KK; s++) {
                if (oth[s] < lst[r][KK - 1]) {
                    lst[r][KK - 1] = oth[s];
#pragma unroll
                    for (int s2 = KK - 1; s2 > 0; --s2) {
                        if (lst[r][s2] < lst[r][s2 - 1]) {
                            unsigned long long tmp = lst[r][s2];
                            lst[r][s2] = lst[r][s2 - 1]; lst[r][s2 - 1] = tmp;
                        }
                    }
                }
            }
        }
    }

    if ((t & 7) == 0) {
#pragma unroll
        for (int r = 0; r < 4; r++) {
            int nrow = nodeBase + qBase + r0 + r;
#pragma unroll
            for (int s = 0; s < KK; s++)
                g_nn[nrow * KK + s] = (int)(unsigned int)(lst[r][s] & 0xFFFFFFFFu);
        }
    }
}

// ---------------- degree (int atomics: deterministic) ----------------
__global__ void deg_kernel() {
    int i = blockIdx.x * blockDim.x + threadIdx.x;
    if (i >= Ec) return;
    int cnt  = edge_count(i);
    int rown = i / KK;              // b*N + n
    int n    = rown & (Nn - 1);
    int m    = g_nn[i];
    int src  = m + cnt * Nn;
    int dst  = n + cnt * Nn;
    if (src < NBc && dst < NBc) atomicAdd(&g_deg[src], 1);
}

__global__ void dinv_kernel() {
    int i = blockIdx.x * blockDim.x + threadIdx.x;
    if (i >= NBc) return;
    int d = g_deg[i];
    g_dinv[i] = (d > 0) ? (1.0f / sqrtf((float)d)) : 0.0f;
}

// ---------------- Tx1: deterministic gather-side aggregation ----------------
// dst = q*N + n receives only from center rows (b', n) with b' in {q-1, q}
// whose edge index i has count(i)==q (linspace-count structure).
__global__ void tx1_kernel() {
    int flat = blockIdx.x * blockDim.x + threadIdx.x;
    if (flat >= NBc * Cc) return;
    int d  = flat / Cc, ch = flat % Cc;
    int q  = d >> 12, n = d & (Nn - 1);
    float dv = g_dinv[d];
    float acc = 0.f;
#pragma unroll
    for (int bb = 0; bb < 2; bb++) {
        int bp = q - 1 + bb;
        if (bp < 0 || bp >= Bc) continue;
        int ibase = (bp * Nn + n) * KK;
#pragma unroll
        for (int j = 0; j < KK; j++) {
            int i = ibase + j;
            if (edge_count(i) == q) {
                int src = g_nn[i] + q * Nn;   // always < NB since q <= 7
                acc = fmaf(-dv * g_dinv[src], g_nodes[src * Cc + ch], acc);
            }
        }
    }
    g_tx1[flat] = acc;
}

// ---------------- epilogue: out = nodes@W0 + Tx1@W1 + bias ----------------
__global__ void out_kernel(const float* __restrict__ W0, const float* __restrict__ W1,
                           const float* __restrict__ bias, float* __restrict__ out) {
    __shared__ float sW0[Cc * Cc], sW1[Cc * Cc], sb[Cc];
    int t = threadIdx.x;
    for (int i = t; i < Cc * Cc; i += blockDim.x) { sW0[i] = W0[i]; sW1[i] = W1[i]; }
    if (t < Cc) sb[t] = bias[t];
    __syncthreads();
    int flat = blockIdx.x * blockDim.x + t;
    if (flat >= NBc * Cc) return;
    int d = flat / Cc, co = flat % Cc;
    const float* nrow = &g_nodes[d * Cc];
    const float* trow = &g_tx1[d * Cc];
    float acc = sb[co];
#pragma unroll
    for (int k = 0; k < Cc; k++)
        acc = fmaf(nrow[k], sW0[k * Cc + co], fmaf(trow[k], sW1[k * Cc + co], acc));
    out[flat] = acc;
}

// ---------------- launch ----------------
extern "C" void kernel_launch(void* const* d_in, const int* in_sizes, int n_in,
                              void* d_out, int out_size) {
    const float* x    = (const float*)d_in[0];
    const float* W0   = (const float*)d_in[1];
    const float* W1   = (const float*)d_in[2];
    const float* bias = (const float*)d_in[3];
    float* out = (float*)d_out;
    (void)in_sizes; (void)n_in; (void)out_size;

    prep_kernel<<<NBc / 256, 256>>>(x);
    dim3 gknn(Nn / QT, Bc);
    knn_kernel<<<gknn, 256>>>();
    deg_kernel<<<(Ec + 255) / 256, 256>>>();
    dinv_kernel<<<NBc / 256, 256>>>();
    tx1_kernel<<<(NBc * Cc) / 256, 256>>>();
    out_kernel<<<(NBc * Cc) / 256, 256>>>(W0, W1, bias, out);
}